// round 15
// baseline (speedup 1.0000x reference)
#include <cuda_runtime.h>
#include <cuda_fp16.h>
#include <cstdint>

#define BATCH 2048
#define KK    64
#define DD    128
#define R1    1024
#define OLEN  512
#define KCAT  1024
#define KC    64
#define NCH   16                 // chunks per k (1024/64)
#define KSPL  2                  // k-split for dense Wr GEMM
#define GTR   ((KK/KSPL)*NCH)    // 512 iters per dense CTA
#define AST   72                 // smem row stride in halves (pad 8)
// --- main_mma tiles: A 64 rows, B 128 rows ---
#define ABYT_A (64*AST*2)        // 9216
#define ABYT_B (128*AST*2)       // 18432
#define STAGE_M (ABYT_A+ABYT_B)  // 27648
#define SMEMM  (3*STAGE_M)       // 82944
// --- gather tiles: A 128, B 128 (unchanged) ---
#define STAGE_G (2*ABYT_B)
#define SMEMG  (3*STAGE_G)
#define ECAP  4096
#define MAXSEG 96

typedef unsigned long long ull;

__device__ float g_d2 [BATCH * KK];
__device__ __half g_Wc_cat[(size_t)KK * OLEN * KCAT];
__device__ __half g_Wr_cat[(size_t)KK * OLEN * KCAT];
__device__ __half g_ucat  [(size_t)BATCH * KCAT];
__device__ int   g_cnt[KK];
__device__ int2  g_eb[(size_t)KK * ECAP];
__device__ int4  g_segs[MAXSEG];
__device__ int   g_nseg;
__device__ float g_xp[KSPL][(size_t)BATCH * OLEN];

__device__ __forceinline__ uint32_t smem_u32(const void* p) {
    uint32_t a;
    asm("{ .reg .u64 t; cvta.to.shared.u64 t, %1; cvt.u32.u64 %0, t; }" : "=r"(a) : "l"(p));
    return a;
}
__device__ __forceinline__ void cpa16(uint32_t dst, const void* src) {
    asm volatile("cp.async.cg.shared.global [%0], [%1], 16;"
                 :: "r"(dst), "l"(__cvta_generic_to_global(src)) : "memory");
}
__device__ __forceinline__ void ldsm4(uint32_t a, uint32_t& r0, uint32_t& r1,
                                      uint32_t& r2, uint32_t& r3) {
    asm volatile("ldmatrix.sync.aligned.m8n8.x4.shared.b16 {%0,%1,%2,%3}, [%4];"
                 : "=r"(r0), "=r"(r1), "=r"(r2), "=r"(r3) : "r"(a));
}
__device__ __forceinline__ void mma16816(float* d, const uint32_t* a, const uint32_t* b) {
    asm volatile("mma.sync.aligned.m16n8k16.row.col.f32.f16.f16.f32 "
                 "{%0,%1,%2,%3}, {%4,%5,%6,%7}, {%8,%9}, {%0,%1,%2,%3};"
                 : "+f"(d[0]), "+f"(d[1]), "+f"(d[2]), "+f"(d[3])
                 : "r"(a[0]), "r"(a[1]), "r"(a[2]), "r"(a[3]), "r"(b[0]), "r"(b[1]));
}
__device__ __forceinline__ ull dup2(float a) {
    ull r; asm("mov.b64 %0, {%1, %1};" : "=l"(r) : "f"(a)); return r;
}
__device__ __forceinline__ void fma2(ull& a, ull x, ull y) {
    asm("fma.rn.f32x2 %0, %1, %2, %0;" : "+l"(a) : "l"(x), "l"(y));
}
__device__ __forceinline__ void unpk2(ull v, float& lo, float& hi) {
    asm("mov.b64 {%0, %1}, %2;" : "=f"(lo), "=f"(hi) : "l"(v));
}

// ---------------- init: zero y-half + reset counters ----------------
__global__ void init_kernel(float* __restrict__ out)
{
    size_t i = ((size_t)blockIdx.x * blockDim.x + threadIdx.x) * 4;
    *(float4*)(out + i) = make_float4(0.f, 0.f, 0.f, 0.f);
    if (blockIdx.x == 0) {
        if (threadIdx.x < KK) g_cnt[threadIdx.x] = 0;
        if (threadIdx.x == 0) g_nseg = 0;
    }
}
__global__ void addx_kernel(float* __restrict__ out)
{
    size_t i = ((size_t)blockIdx.x * blockDim.x + threadIdx.x) * 4;
    float4 a = *(const float4*)(g_xp[0] + i);
    float4 b = *(const float4*)(g_xp[1] + i);
    *(float4*)(out + (size_t)BATCH * OLEN + i) =
        make_float4(a.x + b.x, a.y + b.y, a.z + b.z, a.w + b.w);
}

// ---------------- d2: f32x2-packed ----------------
__global__ void d2_kernel(const float* __restrict__ z, const float* __restrict__ mu,
                          const float* __restrict__ sig)
{
    __shared__ float diffP[16 * DD * 2];
    __shared__ float part[4][32];
    const int k = blockIdx.x, b0 = blockIdx.y * 32, e = threadIdx.x;

    for (int idx = e; idx < 32 * DD; idx += 128) {
        int b = idx >> 7, d = idx & 127;
        diffP[(b >> 1) * 256 + d * 2 + (b & 1)] =
            mu[k * DD + d] - z[(size_t)(b0 + b) * DD + d];
    }
    __syncthreads();

    ull inner2[16];
#pragma unroll
    for (int p = 0; p < 16; p++) inner2[p] = 0ull;

    const float* Ak = sig + (size_t)k * DD * DD + e;
#pragma unroll 2
    for (int d = 0; d < DD; d++) {
        ull a2 = dup2(Ak[(size_t)d * DD]);
        const float* dp = &diffP[d * 2];
#pragma unroll
        for (int p = 0; p < 16; p++)
            fma2(inner2[p], a2, *(const ull*)(dp + p * 256));
    }

    const int lane = e & 31, w = e >> 5;
#pragma unroll
    for (int p = 0; p < 16; p++) {
        float lo, hi; unpk2(inner2[p], lo, hi);
        float v0 = lo * lo, v1 = hi * hi;
#pragma unroll
        for (int off = 16; off > 0; off >>= 1) {
            v0 += __shfl_xor_sync(0xffffffffu, v0, off);
            v1 += __shfl_xor_sync(0xffffffffu, v1, off);
        }
        if (lane == 0) { part[w][2 * p] = v0; part[w][2 * p + 1] = v1; }
    }
    __syncthreads();
    if (e < 32) {
        float d2v = part[0][e] + part[1][e] + part[2][e] + part[3][e];
        g_d2[(size_t)(b0 + e) * KK + k] = fmaxf(d2v, 0.0f);
    }
}

// ---------------- top-2 softmax selection -> buckets ----------------
__global__ void top2_kernel()
{
    const int b = blockIdx.x * blockDim.x + threadIdx.x;
    float v[KK];
    float b1 = 3.4e38f, b2 = 3.4e38f; int k1 = 0, k2 = 1;
#pragma unroll
    for (int k = 0; k < KK; k++) {
        v[k] = g_d2[b * KK + k];
        if (v[k] < b1)      { b2 = b1; k2 = k1; b1 = v[k]; k1 = k; }
        else if (v[k] < b2) { b2 = v[k]; k2 = k; }
    }
    float s = 0.f;
#pragma unroll
    for (int k = 0; k < KK; k++) s += expf(b1 - v[k]);
    const float w1 = 1.f / s;
    const float w2 = expf(b1 - b2) / s;
    int p1 = atomicAdd(&g_cnt[k1], 1);
    g_eb[(size_t)k1 * ECAP + p1] = make_int2(b, __float_as_int(w1));
    int p2 = atomicAdd(&g_cnt[k2], 1);
    g_eb[(size_t)k2 * ECAP + p2] = make_int2(b, __float_as_int(w2));
}

__global__ void seg_kernel()
{
    if (threadIdx.x != 0 || blockIdx.x != 0) return;
    int tot = 0;
    for (int k = 0; k < KK; k++) {
        int c = g_cnt[k];
        for (int j = 0; j * 128 < c; j++) {
            int rows = c - j * 128; if (rows > 128) rows = 128;
            if (tot < MAXSEG) g_segs[tot] = make_int4(k, k * ECAP + j * 128, rows, 0);
            tot++;
        }
    }
    g_nseg = tot < MAXSEG ? tot : MAXSEG;
}

// ---------------- fp32 -> fp16 casts ----------------
__global__ void convw_kernel(const float* __restrict__ W, int sel)
{
    __half* out = sel ? g_Wr_cat : g_Wc_cat;
    size_t e = ((size_t)blockIdx.x * blockDim.x + threadIdx.x) * 4;
    float4 v = *(const float4*)(W + e);
    uint2 ph;
    ph.x = (uint32_t)__half_as_ushort(__float2half_rn(v.x))
         | ((uint32_t)__half_as_ushort(__float2half_rn(v.y)) << 16);
    ph.y = (uint32_t)__half_as_ushort(__float2half_rn(v.z))
         | ((uint32_t)__half_as_ushort(__float2half_rn(v.w)) << 16);
    *(uint2*)(out + e) = ph;
}
__global__ void convu_kernel(const float* __restrict__ U)
{
    size_t e = ((size_t)blockIdx.x * blockDim.x + threadIdx.x) * 4;
    float4 v = *(const float4*)(U + e);
    uint2 ph;
    ph.x = (uint32_t)__half_as_ushort(__float2half_rn(v.x))
         | ((uint32_t)__half_as_ushort(__float2half_rn(v.y)) << 16);
    ph.y = (uint32_t)__half_as_ushort(__float2half_rn(v.z))
         | ((uint32_t)__half_as_ushort(__float2half_rn(v.w)) << 16);
    *(uint2*)(g_ucat + e) = ph;
}

// ---------------- dense Wr GEMM: CTA 64b x 128o, 2 CTAs/SM ----------------
// grid (4 o, 32 b, 2 ksplit), 256 threads (8 warps, 2x4; warp tile 32x32)
__global__ void __launch_bounds__(256, 2)
main_mma(const float* __restrict__ member)
{
    extern __shared__ char dyn[];
    const uint32_t sbase = smem_u32(dyn);
    const int tid = threadIdx.x, lane = tid & 31, wid = tid >> 5;
    const int wm = wid >> 2, wn = wid & 3;
    const int o0 = blockIdx.x * 128, b0 = blockIdx.y * 64, ks = blockIdx.z;
    const int kbase = ks * (KK / KSPL);

    float acc[8][4], run[8][4];
#pragma unroll
    for (int t = 0; t < 8; t++)
#pragma unroll
        for (int r = 0; r < 4; r++) { acc[t][r] = 0.f; run[t][r] = 0.f; }

    for (int g = 0; g < GTR + 2; ++g) {
        __syncthreads();
        if (g < GTR) {
            const int kf = kbase + g / NCH, i0 = (g % NCH) * KC;
            const uint32_t sb = sbase + (g % 3) * STAGE_M;
            const __half* urow = g_ucat + (size_t)b0 * KCAT + i0;
            const __half* wrow = g_Wr_cat + ((size_t)kf * OLEN + o0) * KCAT + i0;
#pragma unroll
            for (int v = 0; v < 2; v++) {          // A: 64 rows
                const int idx = tid + 256 * v, r = idx >> 3, s = idx & 7;
                cpa16(sb + (uint32_t)(r * (AST * 2) + s * 16),
                      urow + (size_t)r * KCAT + s * 8);
            }
#pragma unroll
            for (int v = 0; v < 4; v++) {          // B: 128 rows
                const int idx = tid + 256 * v, r = idx >> 3, s = idx & 7;
                cpa16(sb + ABYT_A + (uint32_t)(r * (AST * 2) + s * 16),
                      wrow + (size_t)r * KCAT + s * 8);
            }
        }
        asm volatile("cp.async.commit_group;" ::: "memory");
        if (g >= 2) {
            const int gm = g - 2;
            asm volatile("cp.async.wait_group 2;" ::: "memory");
            __syncthreads();
            const uint32_t Ab = sbase + (gm % 3) * STAGE_M;
            const uint32_t Bb = Ab + ABYT_A;
#pragma unroll
            for (int kq = 0; kq < 4; kq++) {
                uint32_t a[2][4], b[2][4];
#pragma unroll
                for (int mi = 0; mi < 2; mi++) {
                    const int row = wm * 32 + mi * 16 + (lane & 15);
                    const uint32_t ad = Ab + row * (AST * 2) + kq * 32 + ((lane >> 4) & 1) * 16;
                    ldsm4(ad, a[mi][0], a[mi][1], a[mi][2], a[mi][3]);
                }
#pragma unroll
                for (int np = 0; np < 2; np++) {
                    const int row = wn * 32 + np * 16 + ((lane >> 4) & 1) * 8 + (lane & 7);
                    const uint32_t bd = Bb + row * (AST * 2) + kq * 32 + ((lane >> 3) & 1) * 16;
                    ldsm4(bd, b[np][0], b[np][1], b[np][2], b[np][3]);
                }
#pragma unroll
                for (int mi = 0; mi < 2; mi++)
#pragma unroll
                    for (int ni = 0; ni < 4; ni++)
                        mma16816(acc[mi * 4 + ni], a[mi], &b[ni >> 1][(ni & 1) * 2]);
            }
            if (gm % NCH == NCH - 1) {
                const int k = kbase + gm / NCH;
#pragma unroll
                for (int mi = 0; mi < 2; mi++) {
                    const int r0 = b0 + wm * 32 + mi * 16 + (lane >> 2);
                    const float w0 = __ldg(&member[(size_t)r0 * KK + k]);
                    const float w1 = __ldg(&member[(size_t)(r0 + 8) * KK + k]);
#pragma unroll
                    for (int ni = 0; ni < 4; ni++) {
                        float* A_ = acc[mi * 4 + ni];
                        float* R_ = run[mi * 4 + ni];
                        R_[0] = fmaf(w0, fabsf(A_[0]), R_[0]);
                        R_[1] = fmaf(w0, fabsf(A_[1]), R_[1]);
                        R_[2] = fmaf(w1, fabsf(A_[2]), R_[2]);
                        R_[3] = fmaf(w1, fabsf(A_[3]), R_[3]);
                        A_[0] = A_[1] = A_[2] = A_[3] = 0.f;
                    }
                }
            }
        }
    }

    float* ob = g_xp[ks];
#pragma unroll
    for (int mi = 0; mi < 2; mi++)
#pragma unroll
        for (int ni = 0; ni < 4; ni++) {
            const int row = b0 + wm * 32 + mi * 16 + (lane >> 2);
            const int col = o0 + wn * 32 + ni * 8 + 2 * (lane & 3);
            *(float2*)&ob[(size_t)row * OLEN + col] =
                make_float2(run[mi * 4 + ni][0], run[mi * 4 + ni][1]);
            *(float2*)&ob[(size_t)(row + 8) * OLEN + col] =
                make_float2(run[mi * 4 + ni][2], run[mi * 4 + ni][3]);
        }
}

// ---------------- gathered Wc GEMM (top-2 psi entries) ----------------
__global__ void __launch_bounds__(256, 1)
gather_mma(float* __restrict__ out)
{
    if ((int)blockIdx.y >= g_nseg) return;
    extern __shared__ char dyn[];
    const uint32_t sbase = smem_u32(dyn);
    __shared__ int   rowb[128];
    __shared__ float roww[128];
    const int tid = threadIdx.x, lane = tid & 31, wid = tid >> 5;
    const int wm = wid >> 2, wn = wid & 3;
    const int o0 = blockIdx.x * 128;
    const int4 sgd = g_segs[blockIdx.y];
    const int k = sgd.x, ebase = sgd.y, rows = sgd.z;

    if (tid < 128) {
        if (tid < rows) {
            int2 e = g_eb[(size_t)ebase + tid];
            rowb[tid] = e.x; roww[tid] = __int_as_float(e.y);
        } else { rowb[tid] = 0; roww[tid] = 0.f; }
    }
    __syncthreads();

    float acc[16][4];
#pragma unroll
    for (int t = 0; t < 16; t++)
#pragma unroll
        for (int r = 0; r < 4; r++) acc[t][r] = 0.f;

    for (int g = 0; g < NCH + 2; ++g) {
        __syncthreads();
        if (g < NCH) {
            const int i0 = g * KC;
            const uint32_t sb = sbase + (g % 3) * STAGE_G;
#pragma unroll
            for (int v = 0; v < 4; v++) {
                const int idx = tid + 256 * v, r = idx >> 3, s = idx & 7;
                const uint32_t off = (uint32_t)(r * (AST * 2) + s * 16);
                cpa16(sb + off, g_ucat + (size_t)rowb[r] * KCAT + i0 + s * 8);
                cpa16(sb + ABYT_B + off,
                      g_Wc_cat + ((size_t)k * OLEN + o0 + r) * KCAT + i0 + s * 8);
            }
        }
        asm volatile("cp.async.commit_group;" ::: "memory");
        if (g >= 2) {
            const int gm = g - 2;
            asm volatile("cp.async.wait_group 2;" ::: "memory");
            __syncthreads();
            const uint32_t Ab = sbase + (gm % 3) * STAGE_G;
            const uint32_t Bb = Ab + ABYT_B;
#pragma unroll
            for (int kq = 0; kq < 4; kq++) {
                uint32_t a[4][4], b[2][4];
#pragma unroll
                for (int mi = 0; mi < 4; mi++) {
                    const int row = wm * 64 + mi * 16 + (lane & 15);
                    const uint32_t ad = Ab + row * (AST * 2) + kq * 32 + ((lane >> 4) & 1) * 16;
                    ldsm4(ad, a[mi][0], a[mi][1], a[mi][2], a[mi][3]);
                }
#pragma unroll
                for (int np = 0; np < 2; np++) {
                    const int row = wn * 32 + np * 16 + ((lane >> 4) & 1) * 8 + (lane & 7);
                    const uint32_t bd = Bb + row * (AST * 2) + kq * 32 + ((lane >> 3) & 1) * 16;
                    ldsm4(bd, b[np][0], b[np][1], b[np][2], b[np][3]);
                }
#pragma unroll
                for (int mi = 0; mi < 4; mi++)
#pragma unroll
                    for (int ni = 0; ni < 4; ni++)
                        mma16816(acc[mi * 4 + ni], a[mi], &b[ni >> 1][(ni & 1) * 2]);
            }
        }
    }

#pragma unroll
    for (int mi = 0; mi < 4; mi++) {
        const int lr0 = wm * 64 + mi * 16 + (lane >> 2);
        const int lr1 = lr0 + 8;
        const float w0 = roww[lr0], w1 = roww[lr1];
        const int   bb0 = rowb[lr0], bb1 = rowb[lr1];
#pragma unroll
        for (int ni = 0; ni < 4; ni++) {
            const int col = o0 + wn * 32 + ni * 8 + 2 * (lane & 3);
            float* A_ = acc[mi * 4 + ni];
            if (w0 != 0.f) {
                atomicAdd(&out[(size_t)bb0 * OLEN + col],     w0 * fabsf(A_[0]));
                atomicAdd(&out[(size_t)bb0 * OLEN + col + 1], w0 * fabsf(A_[1]));
            }
            if (w1 != 0.f) {
                atomicAdd(&out[(size_t)bb1 * OLEN + col],     w1 * fabsf(A_[2]));
                atomicAdd(&out[(size_t)bb1 * OLEN + col + 1], w1 * fabsf(A_[3]));
            }
        }
    }
}

// =================================================================
extern "C" void kernel_launch(void* const* d_in, const int* in_sizes, int n_in,
                              void* d_out, int out_size)
{
    const float* z   = (const float*)d_in[0];
    const float* u   = (const float*)d_in[1];
    const float* mem = (const float*)d_in[2];
    const float* mu  = (const float*)d_in[3];
    const float* sig = (const float*)d_in[4];
    const float* Wc  = (const float*)d_in[5];
    const float* Wr  = (const float*)d_in[6];
    float* out = (float*)d_out;

    cudaFuncSetAttribute(main_mma,   cudaFuncAttributeMaxDynamicSharedMemorySize, SMEMM);
    cudaFuncSetAttribute(gather_mma, cudaFuncAttributeMaxDynamicSharedMemorySize, SMEMG);

    init_kernel<<<(BATCH * OLEN / 4) / 256, 256>>>(out);                 // 1
    convw_kernel<<<(KK * OLEN * R1 / 4) / 256, 256>>>(Wr, 1);            // 2
    convu_kernel<<<(BATCH * R1 / 4) / 256, 256>>>(u);                    // 3
    main_mma<<<dim3(OLEN / 128, BATCH / 64, KSPL), 256, SMEMM>>>(mem);   // 4 <- ncu
    convw_kernel<<<(KK * OLEN * R1 / 4) / 256, 256>>>(Wc, 0);            // 5
    d2_kernel<<<dim3(KK, BATCH / 32), 128>>>(z, mu, sig);                // 6
    top2_kernel<<<BATCH / 256, 256>>>();                                 // 7
    seg_kernel<<<1, 32>>>();                                             // 8
    addx_kernel<<<(BATCH * OLEN / 4) / 256, 256>>>(out);                 // 9
    gather_mma<<<dim3(OLEN / 128, MAXSEG), 256, SMEMG>>>(out);           // 10
}

// round 16
// speedup vs baseline: 1.0938x; 1.0938x over previous
#include <cuda_runtime.h>
#include <cuda_fp16.h>
#include <cstdint>

#define BATCH 2048
#define KK    64
#define DD    128
#define R1    1024
#define OLEN  512
#define KCAT  1024
#define KC    64
#define NCH   16                 // chunks per k (1024/64)
#define KSPL  2                  // k-split for dense Wr GEMM
#define GTR   ((KK/KSPL)*NCH)    // 512 iters per dense CTA
#define AST   72                 // smem row stride in halves (pad 8)
// --- main_mma tiles: A 64 rows, B 128 rows, 4 stages ---
#define ABYT_A (64*AST*2)        // 9216
#define ABYT_B (128*AST*2)       // 18432
#define STAGE_M (ABYT_A+ABYT_B)  // 27648
#define NST   4
#define SMEMM  (NST*STAGE_M)     // 110592
// --- gather tiles: A 128, B 128, 3 stages (unchanged) ---
#define STAGE_G (2*ABYT_B)
#define SMEMG  (3*STAGE_G)
#define ECAP  4096
#define MAXSEG 96

typedef unsigned long long ull;

__device__ float g_d2 [BATCH * KK];
__device__ __half g_Wc_cat[(size_t)KK * OLEN * KCAT];
__device__ __half g_Wr_cat[(size_t)KK * OLEN * KCAT];
__device__ __half g_ucat  [(size_t)BATCH * KCAT];
__device__ int   g_cnt[KK];
__device__ int2  g_eb[(size_t)KK * ECAP];
__device__ int4  g_segs[MAXSEG];
__device__ int   g_nseg;
__device__ float g_xp[KSPL][(size_t)BATCH * OLEN];

__device__ __forceinline__ uint32_t smem_u32(const void* p) {
    uint32_t a;
    asm("{ .reg .u64 t; cvta.to.shared.u64 t, %1; cvt.u32.u64 %0, t; }" : "=r"(a) : "l"(p));
    return a;
}
__device__ __forceinline__ void cpa16(uint32_t dst, const void* src) {
    asm volatile("cp.async.cg.shared.global [%0], [%1], 16;"
                 :: "r"(dst), "l"(__cvta_generic_to_global(src)) : "memory");
}
__device__ __forceinline__ void ldsm4(uint32_t a, uint32_t& r0, uint32_t& r1,
                                      uint32_t& r2, uint32_t& r3) {
    asm volatile("ldmatrix.sync.aligned.m8n8.x4.shared.b16 {%0,%1,%2,%3}, [%4];"
                 : "=r"(r0), "=r"(r1), "=r"(r2), "=r"(r3) : "r"(a));
}
__device__ __forceinline__ void mma16816(float* d, const uint32_t* a, const uint32_t* b) {
    asm volatile("mma.sync.aligned.m16n8k16.row.col.f32.f16.f16.f32 "
                 "{%0,%1,%2,%3}, {%4,%5,%6,%7}, {%8,%9}, {%0,%1,%2,%3};"
                 : "+f"(d[0]), "+f"(d[1]), "+f"(d[2]), "+f"(d[3])
                 : "r"(a[0]), "r"(a[1]), "r"(a[2]), "r"(a[3]), "r"(b[0]), "r"(b[1]));
}
__device__ __forceinline__ ull dup2(float a) {
    ull r; asm("mov.b64 %0, {%1, %1};" : "=l"(r) : "f"(a)); return r;
}
__device__ __forceinline__ void fma2(ull& a, ull x, ull y) {
    asm("fma.rn.f32x2 %0, %1, %2, %0;" : "+l"(a) : "l"(x), "l"(y));
}
__device__ __forceinline__ void unpk2(ull v, float& lo, float& hi) {
    asm("mov.b64 {%0, %1}, %2;" : "=f"(lo), "=f"(hi) : "l"(v));
}

// ---------------- init: zero y-half + reset counters ----------------
__global__ void init_kernel(float* __restrict__ out)
{
    size_t i = ((size_t)blockIdx.x * blockDim.x + threadIdx.x) * 4;
    *(float4*)(out + i) = make_float4(0.f, 0.f, 0.f, 0.f);
    if (blockIdx.x == 0) {
        if (threadIdx.x < KK) g_cnt[threadIdx.x] = 0;
        if (threadIdx.x == 0) g_nseg = 0;
    }
}
__global__ void addx_kernel(float* __restrict__ out)
{
    size_t i = ((size_t)blockIdx.x * blockDim.x + threadIdx.x) * 4;
    float4 a = *(const float4*)(g_xp[0] + i);
    float4 b = *(const float4*)(g_xp[1] + i);
    *(float4*)(out + (size_t)BATCH * OLEN + i) =
        make_float4(a.x + b.x, a.y + b.y, a.z + b.z, a.w + b.w);
}

// ---------------- d2: f32x2-packed ----------------
__global__ void d2_kernel(const float* __restrict__ z, const float* __restrict__ mu,
                          const float* __restrict__ sig)
{
    __shared__ float diffP[16 * DD * 2];
    __shared__ float part[4][32];
    const int k = blockIdx.x, b0 = blockIdx.y * 32, e = threadIdx.x;

    for (int idx = e; idx < 32 * DD; idx += 128) {
        int b = idx >> 7, d = idx & 127;
        diffP[(b >> 1) * 256 + d * 2 + (b & 1)] =
            mu[k * DD + d] - z[(size_t)(b0 + b) * DD + d];
    }
    __syncthreads();

    ull inner2[16];
#pragma unroll
    for (int p = 0; p < 16; p++) inner2[p] = 0ull;

    const float* Ak = sig + (size_t)k * DD * DD + e;
#pragma unroll 2
    for (int d = 0; d < DD; d++) {
        ull a2 = dup2(Ak[(size_t)d * DD]);
        const float* dp = &diffP[d * 2];
#pragma unroll
        for (int p = 0; p < 16; p++)
            fma2(inner2[p], a2, *(const ull*)(dp + p * 256));
    }

    const int lane = e & 31, w = e >> 5;
#pragma unroll
    for (int p = 0; p < 16; p++) {
        float lo, hi; unpk2(inner2[p], lo, hi);
        float v0 = lo * lo, v1 = hi * hi;
#pragma unroll
        for (int off = 16; off > 0; off >>= 1) {
            v0 += __shfl_xor_sync(0xffffffffu, v0, off);
            v1 += __shfl_xor_sync(0xffffffffu, v1, off);
        }
        if (lane == 0) { part[w][2 * p] = v0; part[w][2 * p + 1] = v1; }
    }
    __syncthreads();
    if (e < 32) {
        float d2v = part[0][e] + part[1][e] + part[2][e] + part[3][e];
        g_d2[(size_t)(b0 + e) * KK + k] = fmaxf(d2v, 0.0f);
    }
}

// ---------------- top-2 softmax selection -> buckets ----------------
__global__ void top2_kernel()
{
    const int b = blockIdx.x * blockDim.x + threadIdx.x;
    float v[KK];
    float b1 = 3.4e38f, b2 = 3.4e38f; int k1 = 0, k2 = 1;
#pragma unroll
    for (int k = 0; k < KK; k++) {
        v[k] = g_d2[b * KK + k];
        if (v[k] < b1)      { b2 = b1; k2 = k1; b1 = v[k]; k1 = k; }
        else if (v[k] < b2) { b2 = v[k]; k2 = k; }
    }
    float s = 0.f;
#pragma unroll
    for (int k = 0; k < KK; k++) s += expf(b1 - v[k]);
    const float w1 = 1.f / s;
    const float w2 = expf(b1 - b2) / s;
    int p1 = atomicAdd(&g_cnt[k1], 1);
    g_eb[(size_t)k1 * ECAP + p1] = make_int2(b, __float_as_int(w1));
    int p2 = atomicAdd(&g_cnt[k2], 1);
    g_eb[(size_t)k2 * ECAP + p2] = make_int2(b, __float_as_int(w2));
}

__global__ void seg_kernel()
{
    if (threadIdx.x != 0 || blockIdx.x != 0) return;
    int tot = 0;
    for (int k = 0; k < KK; k++) {
        int c = g_cnt[k];
        for (int j = 0; j * 128 < c; j++) {
            int rows = c - j * 128; if (rows > 128) rows = 128;
            if (tot < MAXSEG) g_segs[tot] = make_int4(k, k * ECAP + j * 128, rows, 0);
            tot++;
        }
    }
    g_nseg = tot < MAXSEG ? tot : MAXSEG;
}

// ---------------- fp32 -> fp16 casts ----------------
__global__ void convw_kernel(const float* __restrict__ W, int sel)
{
    __half* out = sel ? g_Wr_cat : g_Wc_cat;
    size_t e = ((size_t)blockIdx.x * blockDim.x + threadIdx.x) * 4;
    float4 v = *(const float4*)(W + e);
    uint2 ph;
    ph.x = (uint32_t)__half_as_ushort(__float2half_rn(v.x))
         | ((uint32_t)__half_as_ushort(__float2half_rn(v.y)) << 16);
    ph.y = (uint32_t)__half_as_ushort(__float2half_rn(v.z))
         | ((uint32_t)__half_as_ushort(__float2half_rn(v.w)) << 16);
    *(uint2*)(out + e) = ph;
}
__global__ void convu_kernel(const float* __restrict__ U)
{
    size_t e = ((size_t)blockIdx.x * blockDim.x + threadIdx.x) * 4;
    float4 v = *(const float4*)(U + e);
    uint2 ph;
    ph.x = (uint32_t)__half_as_ushort(__float2half_rn(v.x))
         | ((uint32_t)__half_as_ushort(__float2half_rn(v.y)) << 16);
    ph.y = (uint32_t)__half_as_ushort(__float2half_rn(v.z))
         | ((uint32_t)__half_as_ushort(__float2half_rn(v.w)) << 16);
    *(uint2*)(g_ucat + e) = ph;
}

// ---------------- dense Wr GEMM: 64b x 128o, 4-stage, 1 sync/chunk ----------------
// grid (4 o, 32 b, 2 ksplit), 256 threads (8 warps, 2x4; warp tile 32x32)
__global__ void __launch_bounds__(256, 2)
main_mma(const float* __restrict__ member)
{
    extern __shared__ char dyn[];
    const uint32_t sbase = smem_u32(dyn);
    const int tid = threadIdx.x, lane = tid & 31, wid = tid >> 5;
    const int wm = wid >> 2, wn = wid & 3;
    const int o0 = blockIdx.x * 128, b0 = blockIdx.y * 64, ks = blockIdx.z;
    const int kbase = ks * (KK / KSPL);

    // precomputed per-thread staging offsets
    uint32_t soA[2], soB[4], goA[2], goB[4];
#pragma unroll
    for (int v = 0; v < 2; v++) {
        const int idx = tid + 256 * v, r = idx >> 3, s = idx & 7;
        soA[v] = (uint32_t)(r * (AST * 2) + s * 16);
        goA[v] = (uint32_t)(r * KCAT + s * 8);
    }
#pragma unroll
    for (int v = 0; v < 4; v++) {
        const int idx = tid + 256 * v, r = idx >> 3, s = idx & 7;
        soB[v] = (uint32_t)(ABYT_A + r * (AST * 2) + s * 16);
        goB[v] = (uint32_t)(r * KCAT + s * 8);
    }

    float acc[8][4], run[8][4];
#pragma unroll
    for (int t = 0; t < 8; t++)
#pragma unroll
        for (int r = 0; r < 4; r++) { acc[t][r] = 0.f; run[t][r] = 0.f; }

    for (int g = 0; g < GTR + 2; ++g) {
        if (g < GTR) {
            const int kf = kbase + g / NCH, i0 = (g % NCH) * KC;
            const uint32_t sb = sbase + (g % NST) * STAGE_M;
            const __half* up = g_ucat + (size_t)b0 * KCAT + i0;
            const __half* wp = g_Wr_cat + ((size_t)kf * OLEN + o0) * KCAT + i0;
#pragma unroll
            for (int v = 0; v < 2; v++) cpa16(sb + soA[v], up + goA[v]);
#pragma unroll
            for (int v = 0; v < 4; v++) cpa16(sb + soB[v], wp + goB[v]);
        }
        asm volatile("cp.async.commit_group;" ::: "memory");
        if (g >= 2) {
            const int gm = g - 2;
            asm volatile("cp.async.wait_group 2;" ::: "memory");
            __syncthreads();                         // single barrier per chunk
            const uint32_t Ab = sbase + (gm % NST) * STAGE_M;
            const uint32_t Bb = Ab + ABYT_A;
#pragma unroll
            for (int kq = 0; kq < 4; kq++) {
                uint32_t a[2][4], b[2][4];
#pragma unroll
                for (int mi = 0; mi < 2; mi++) {
                    const int row = wm * 32 + mi * 16 + (lane & 15);
                    const uint32_t ad = Ab + row * (AST * 2) + kq * 32 + ((lane >> 4) & 1) * 16;
                    ldsm4(ad, a[mi][0], a[mi][1], a[mi][2], a[mi][3]);
                }
#pragma unroll
                for (int np = 0; np < 2; np++) {
                    const int row = wn * 32 + np * 16 + ((lane >> 4) & 1) * 8 + (lane & 7);
                    const uint32_t bd = Bb + row * (AST * 2) + kq * 32 + ((lane >> 3) & 1) * 16;
                    ldsm4(bd, b[np][0], b[np][1], b[np][2], b[np][3]);
                }
#pragma unroll
                for (int mi = 0; mi < 2; mi++)
#pragma unroll
                    for (int ni = 0; ni < 4; ni++)
                        mma16816(acc[mi * 4 + ni], a[mi], &b[ni >> 1][(ni & 1) * 2]);
            }
            if (gm % NCH == NCH - 1) {
                const int k = kbase + gm / NCH;
#pragma unroll
                for (int mi = 0; mi < 2; mi++) {
                    const int r0 = b0 + wm * 32 + mi * 16 + (lane >> 2);
                    const float w0 = __ldg(&member[(size_t)r0 * KK + k]);
                    const float w1 = __ldg(&member[(size_t)(r0 + 8) * KK + k]);
#pragma unroll
                    for (int ni = 0; ni < 4; ni++) {
                        float* A_ = acc[mi * 4 + ni];
                        float* R_ = run[mi * 4 + ni];
                        R_[0] = fmaf(w0, fabsf(A_[0]), R_[0]);
                        R_[1] = fmaf(w0, fabsf(A_[1]), R_[1]);
                        R_[2] = fmaf(w1, fabsf(A_[2]), R_[2]);
                        R_[3] = fmaf(w1, fabsf(A_[3]), R_[3]);
                        A_[0] = A_[1] = A_[2] = A_[3] = 0.f;
                    }
                }
            }
        }
    }

    float* ob = g_xp[ks];
#pragma unroll
    for (int mi = 0; mi < 2; mi++)
#pragma unroll
        for (int ni = 0; ni < 4; ni++) {
            const int row = b0 + wm * 32 + mi * 16 + (lane >> 2);
            const int col = o0 + wn * 32 + ni * 8 + 2 * (lane & 3);
            *(float2*)&ob[(size_t)row * OLEN + col] =
                make_float2(run[mi * 4 + ni][0], run[mi * 4 + ni][1]);
            *(float2*)&ob[(size_t)(row + 8) * OLEN + col] =
                make_float2(run[mi * 4 + ni][2], run[mi * 4 + ni][3]);
        }
}

// ---------------- gathered Wc GEMM (top-2 psi entries) ----------------
__global__ void __launch_bounds__(256, 1)
gather_mma(float* __restrict__ out)
{
    if ((int)blockIdx.y >= g_nseg) return;
    extern __shared__ char dyn[];
    const uint32_t sbase = smem_u32(dyn);
    __shared__ int   rowb[128];
    __shared__ float roww[128];
    const int tid = threadIdx.x, lane = tid & 31, wid = tid >> 5;
    const int wm = wid >> 2, wn = wid & 3;
    const int o0 = blockIdx.x * 128;
    const int4 sgd = g_segs[blockIdx.y];
    const int k = sgd.x, ebase = sgd.y, rows = sgd.z;

    if (tid < 128) {
        if (tid < rows) {
            int2 e = g_eb[(size_t)ebase + tid];
            rowb[tid] = e.x; roww[tid] = __int_as_float(e.y);
        } else { rowb[tid] = 0; roww[tid] = 0.f; }
    }
    __syncthreads();

    float acc[16][4];
#pragma unroll
    for (int t = 0; t < 16; t++)
#pragma unroll
        for (int r = 0; r < 4; r++) acc[t][r] = 0.f;

    for (int g = 0; g < NCH + 2; ++g) {
        __syncthreads();
        if (g < NCH) {
            const int i0 = g * KC;
            const uint32_t sb = sbase + (g % 3) * STAGE_G;
#pragma unroll
            for (int v = 0; v < 4; v++) {
                const int idx = tid + 256 * v, r = idx >> 3, s = idx & 7;
                const uint32_t off = (uint32_t)(r * (AST * 2) + s * 16);
                cpa16(sb + off, g_ucat + (size_t)rowb[r] * KCAT + i0 + s * 8);
                cpa16(sb + ABYT_B + off,
                      g_Wc_cat + ((size_t)k * OLEN + o0 + r) * KCAT + i0 + s * 8);
            }
        }
        asm volatile("cp.async.commit_group;" ::: "memory");
        if (g >= 2) {
            const int gm = g - 2;
            asm volatile("cp.async.wait_group 2;" ::: "memory");
            __syncthreads();
            const uint32_t Ab = sbase + (gm % 3) * STAGE_G;
            const uint32_t Bb = Ab + ABYT_B;
#pragma unroll
            for (int kq = 0; kq < 4; kq++) {
                uint32_t a[4][4], b[2][4];
#pragma unroll
                for (int mi = 0; mi < 4; mi++) {
                    const int row = wm * 64 + mi * 16 + (lane & 15);
                    const uint32_t ad = Ab + row * (AST * 2) + kq * 32 + ((lane >> 4) & 1) * 16;
                    ldsm4(ad, a[mi][0], a[mi][1], a[mi][2], a[mi][3]);
                }
#pragma unroll
                for (int np = 0; np < 2; np++) {
                    const int row = wn * 32 + np * 16 + ((lane >> 4) & 1) * 8 + (lane & 7);
                    const uint32_t bd = Bb + row * (AST * 2) + kq * 32 + ((lane >> 3) & 1) * 16;
                    ldsm4(bd, b[np][0], b[np][1], b[np][2], b[np][3]);
                }
#pragma unroll
                for (int mi = 0; mi < 4; mi++)
#pragma unroll
                    for (int ni = 0; ni < 4; ni++)
                        mma16816(acc[mi * 4 + ni], a[mi], &b[ni >> 1][(ni & 1) * 2]);
            }
        }
    }

#pragma unroll
    for (int mi = 0; mi < 4; mi++) {
        const int lr0 = wm * 64 + mi * 16 + (lane >> 2);
        const int lr1 = lr0 + 8;
        const float w0 = roww[lr0], w1 = roww[lr1];
        const int   bb0 = rowb[lr0], bb1 = rowb[lr1];
#pragma unroll
        for (int ni = 0; ni < 4; ni++) {
            const int col = o0 + wn * 32 + ni * 8 + 2 * (lane & 3);
            float* A_ = acc[mi * 4 + ni];
            if (w0 != 0.f) {
                atomicAdd(&out[(size_t)bb0 * OLEN + col],     w0 * fabsf(A_[0]));
                atomicAdd(&out[(size_t)bb0 * OLEN + col + 1], w0 * fabsf(A_[1]));
            }
            if (w1 != 0.f) {
                atomicAdd(&out[(size_t)bb1 * OLEN + col],     w1 * fabsf(A_[2]));
                atomicAdd(&out[(size_t)bb1 * OLEN + col + 1], w1 * fabsf(A_[3]));
            }
        }
    }
}

// =================================================================
extern "C" void kernel_launch(void* const* d_in, const int* in_sizes, int n_in,
                              void* d_out, int out_size)
{
    const float* z   = (const float*)d_in[0];
    const float* u   = (const float*)d_in[1];
    const float* mem = (const float*)d_in[2];
    const float* mu  = (const float*)d_in[3];
    const float* sig = (const float*)d_in[4];
    const float* Wc  = (const float*)d_in[5];
    const float* Wr  = (const float*)d_in[6];
    float* out = (float*)d_out;

    cudaFuncSetAttribute(main_mma,   cudaFuncAttributeMaxDynamicSharedMemorySize, SMEMM);
    cudaFuncSetAttribute(gather_mma, cudaFuncAttributeMaxDynamicSharedMemorySize, SMEMG);

    init_kernel<<<(BATCH * OLEN / 4) / 256, 256>>>(out);                 // 1
    convw_kernel<<<(KK * OLEN * R1 / 4) / 256, 256>>>(Wr, 1);            // 2
    convu_kernel<<<(BATCH * R1 / 4) / 256, 256>>>(u);                    // 3
    main_mma<<<dim3(OLEN / 128, BATCH / 64, KSPL), 256, SMEMM>>>(mem);   // 4 <- ncu
    convw_kernel<<<(KK * OLEN * R1 / 4) / 256, 256>>>(Wc, 0);            // 5
    d2_kernel<<<dim3(KK, BATCH / 32), 128>>>(z, mu, sig);                // 6
    top2_kernel<<<BATCH / 256, 256>>>();                                 // 7
    seg_kernel<<<1, 32>>>();                                             // 8
    addx_kernel<<<(BATCH * OLEN / 4) / 256, 256>>>(out);                 // 9
    gather_mma<<<dim3(OLEN / 128, MAXSEG), 256, SMEMG>>>(out);           // 10
}

// round 17
// speedup vs baseline: 1.1054x; 1.0106x over previous
#include <cuda_runtime.h>
#include <cuda_fp16.h>
#include <cstdint>

#define BATCH 2048
#define KK    64
#define DD    128
#define R1    1024
#define OLEN  512
#define KCAT  1024
#define KC    64
#define NCH   16                 // chunks per k (1024/64)
#define KSPL  2                  // k-split for dense Wr GEMM
#define GTR   ((KK/KSPL)*NCH)    // 512 iters per dense CTA
#define AST   72                 // smem row stride in halves (pad 8)
// --- main_mma tiles: A 64 rows, B 128 rows, 4 stages ---
#define ABYT_A (64*AST*2)        // 9216
#define ABYT_B (128*AST*2)       // 18432
#define STAGE_M (ABYT_A+ABYT_B)  // 27648
#define NST   4
#define SMEMM  (NST*STAGE_M)     // 110592
// --- gather tiles: A 128, B 128, 3 stages ---
#define STAGE_G (2*ABYT_B)
#define SMEMG  (3*STAGE_G)
#define ECAP  4096
#define MAXSEG 96
// conv_all grid partition
#define NB_W  32768              // Wr convert blocks
#define NB_U  2048               // u convert blocks
#define NB_Z  1024               // y-zero blocks

typedef unsigned long long ull;

__device__ float g_d2 [BATCH * KK];
__device__ __half g_Wc_cat[(size_t)KK * OLEN * KCAT];
__device__ __half g_Wr_cat[(size_t)KK * OLEN * KCAT];
__device__ __half g_ucat  [(size_t)BATCH * KCAT];
__device__ int   g_cnt[KK];
__device__ int2  g_eb[(size_t)KK * ECAP];
__device__ int4  g_segs[MAXSEG];
__device__ int   g_nseg;
__device__ float g_xp[KSPL][(size_t)BATCH * OLEN];

__device__ __forceinline__ uint32_t smem_u32(const void* p) {
    uint32_t a;
    asm("{ .reg .u64 t; cvta.to.shared.u64 t, %1; cvt.u32.u64 %0, t; }" : "=r"(a) : "l"(p));
    return a;
}
__device__ __forceinline__ void cpa16(uint32_t dst, const void* src) {
    asm volatile("cp.async.cg.shared.global [%0], [%1], 16;"
                 :: "r"(dst), "l"(__cvta_generic_to_global(src)) : "memory");
}
__device__ __forceinline__ void ldsm4(uint32_t a, uint32_t& r0, uint32_t& r1,
                                      uint32_t& r2, uint32_t& r3) {
    asm volatile("ldmatrix.sync.aligned.m8n8.x4.shared.b16 {%0,%1,%2,%3}, [%4];"
                 : "=r"(r0), "=r"(r1), "=r"(r2), "=r"(r3) : "r"(a));
}
__device__ __forceinline__ void mma16816(float* d, const uint32_t* a, const uint32_t* b) {
    asm volatile("mma.sync.aligned.m16n8k16.row.col.f32.f16.f16.f32 "
                 "{%0,%1,%2,%3}, {%4,%5,%6,%7}, {%8,%9}, {%0,%1,%2,%3};"
                 : "+f"(d[0]), "+f"(d[1]), "+f"(d[2]), "+f"(d[3])
                 : "r"(a[0]), "r"(a[1]), "r"(a[2]), "r"(a[3]), "r"(b[0]), "r"(b[1]));
}
__device__ __forceinline__ ull dup2(float a) {
    ull r; asm("mov.b64 %0, {%1, %1};" : "=l"(r) : "f"(a)); return r;
}
__device__ __forceinline__ void fma2(ull& a, ull x, ull y) {
    asm("fma.rn.f32x2 %0, %1, %2, %0;" : "+l"(a) : "l"(x), "l"(y));
}
__device__ __forceinline__ void unpk2(ull v, float& lo, float& hi) {
    asm("mov.b64 {%0, %1}, %2;" : "=f"(lo), "=f"(hi) : "l"(v));
}
__device__ __forceinline__ uint2 cvt4(float4 v) {
    uint2 p;
    p.x = (uint32_t)__half_as_ushort(__float2half_rn(v.x))
        | ((uint32_t)__half_as_ushort(__float2half_rn(v.y)) << 16);
    p.y = (uint32_t)__half_as_ushort(__float2half_rn(v.z))
        | ((uint32_t)__half_as_ushort(__float2half_rn(v.w)) << 16);
    return p;
}

// ---------------- fused conversions + init ----------------
// blocks [0,NB_W): Wr f32->f16 ; [NB_W,NB_W+NB_U): u ; rest: zero y + reset
__global__ void conv_all(const float* __restrict__ Wr, const float* __restrict__ U,
                         float* __restrict__ out)
{
    const int bid = blockIdx.x;
    if (bid < NB_W) {
        size_t e = ((size_t)bid * 256 + threadIdx.x) * 4;
        *(uint2*)(g_Wr_cat + e) = cvt4(*(const float4*)(Wr + e));
    } else if (bid < NB_W + NB_U) {
        size_t e = ((size_t)(bid - NB_W) * 256 + threadIdx.x) * 4;
        *(uint2*)(g_ucat + e) = cvt4(*(const float4*)(U + e));
    } else {
        const int b3 = bid - NB_W - NB_U;
        size_t i = ((size_t)b3 * 256 + threadIdx.x) * 4;
        *(float4*)(out + i) = make_float4(0.f, 0.f, 0.f, 0.f);
        if (b3 == 0) {
            if (threadIdx.x < KK) g_cnt[threadIdx.x] = 0;
            if (threadIdx.x == 0) g_nseg = 0;
        }
    }
}
__global__ void convw_kernel(const float* __restrict__ W, int sel)
{
    __half* out = sel ? g_Wr_cat : g_Wc_cat;
    size_t e = ((size_t)blockIdx.x * blockDim.x + threadIdx.x) * 4;
    *(uint2*)(out + e) = cvt4(*(const float4*)(W + e));
}
__global__ void addx_kernel(float* __restrict__ out)
{
    size_t i = ((size_t)blockIdx.x * blockDim.x + threadIdx.x) * 4;
    float4 a = *(const float4*)(g_xp[0] + i);
    float4 b = *(const float4*)(g_xp[1] + i);
    *(float4*)(out + (size_t)BATCH * OLEN + i) =
        make_float4(a.x + b.x, a.y + b.y, a.z + b.z, a.w + b.w);
}

// ---------------- d2: f32x2-packed ----------------
__global__ void d2_kernel(const float* __restrict__ z, const float* __restrict__ mu,
                          const float* __restrict__ sig)
{
    __shared__ float diffP[16 * DD * 2];
    __shared__ float part[4][32];
    const int k = blockIdx.x, b0 = blockIdx.y * 32, e = threadIdx.x;

    for (int idx = e; idx < 32 * DD; idx += 128) {
        int b = idx >> 7, d = idx & 127;
        diffP[(b >> 1) * 256 + d * 2 + (b & 1)] =
            mu[k * DD + d] - z[(size_t)(b0 + b) * DD + d];
    }
    __syncthreads();

    ull inner2[16];
#pragma unroll
    for (int p = 0; p < 16; p++) inner2[p] = 0ull;

    const float* Ak = sig + (size_t)k * DD * DD + e;
#pragma unroll 2
    for (int d = 0; d < DD; d++) {
        ull a2 = dup2(Ak[(size_t)d * DD]);
        const float* dp = &diffP[d * 2];
#pragma unroll
        for (int p = 0; p < 16; p++)
            fma2(inner2[p], a2, *(const ull*)(dp + p * 256));
    }

    const int lane = e & 31, w = e >> 5;
#pragma unroll
    for (int p = 0; p < 16; p++) {
        float lo, hi; unpk2(inner2[p], lo, hi);
        float v0 = lo * lo, v1 = hi * hi;
#pragma unroll
        for (int off = 16; off > 0; off >>= 1) {
            v0 += __shfl_xor_sync(0xffffffffu, v0, off);
            v1 += __shfl_xor_sync(0xffffffffu, v1, off);
        }
        if (lane == 0) { part[w][2 * p] = v0; part[w][2 * p + 1] = v1; }
    }
    __syncthreads();
    if (e < 32) {
        float d2v = part[0][e] + part[1][e] + part[2][e] + part[3][e];
        g_d2[(size_t)(b0 + e) * KK + k] = fmaxf(d2v, 0.0f);
    }
}

// ---------------- top-2 selection: warp per b-row ----------------
__global__ void top2_kernel()
{
    const int b = (blockIdx.x * blockDim.x + threadIdx.x) >> 5;
    const int lane = threadIdx.x & 31;
    const float va = g_d2[(size_t)b * KK + lane];
    const float vb = g_d2[(size_t)b * KK + 32 + lane];
    float m1, m2; int k1, k2;
    if (va <= vb) { m1 = va; k1 = lane;      m2 = vb; k2 = lane + 32; }
    else          { m1 = vb; k1 = lane + 32; m2 = va; k2 = lane; }
#pragma unroll
    for (int off = 16; off > 0; off >>= 1) {
        float om1 = __shfl_xor_sync(0xffffffffu, m1, off);
        int   ok1 = __shfl_xor_sync(0xffffffffu, k1, off);
        float om2 = __shfl_xor_sync(0xffffffffu, m2, off);
        int   ok2 = __shfl_xor_sync(0xffffffffu, k2, off);
        if (om1 < m1) {
            if (om2 < m1) { m2 = om2; k2 = ok2; } else { m2 = m1; k2 = k1; }
            m1 = om1; k1 = ok1;
        } else if (om1 < m2) { m2 = om1; k2 = ok1; }
    }
    float s = __expf(m1 - va) + __expf(m1 - vb);
#pragma unroll
    for (int off = 16; off > 0; off >>= 1) s += __shfl_xor_sync(0xffffffffu, s, off);
    if (lane == 0) {
        const float w1 = 1.f / s;
        const float w2 = __expf(m1 - m2) / s;
        int p1 = atomicAdd(&g_cnt[k1], 1);
        g_eb[(size_t)k1 * ECAP + p1] = make_int2(b, __float_as_int(w1));
        int p2 = atomicAdd(&g_cnt[k2], 1);
        g_eb[(size_t)k2 * ECAP + p2] = make_int2(b, __float_as_int(w2));
    }
}

__global__ void seg_kernel()
{
    if (threadIdx.x != 0 || blockIdx.x != 0) return;
    int tot = 0;
    for (int k = 0; k < KK; k++) {
        int c = g_cnt[k];
        for (int j = 0; j * 128 < c; j++) {
            int rows = c - j * 128; if (rows > 128) rows = 128;
            if (tot < MAXSEG) g_segs[tot] = make_int4(k, k * ECAP + j * 128, rows, 0);
            tot++;
        }
    }
    g_nseg = tot < MAXSEG ? tot : MAXSEG;
}

// ---------------- dense Wr GEMM: 64b x 128o, 4-stage, 1 sync/chunk ----------------
__global__ void __launch_bounds__(256, 2)
main_mma(const float* __restrict__ member)
{
    extern __shared__ char dyn[];
    const uint32_t sbase = smem_u32(dyn);
    const int tid = threadIdx.x, lane = tid & 31, wid = tid >> 5;
    const int wm = wid >> 2, wn = wid & 3;
    const int o0 = blockIdx.x * 128, b0 = blockIdx.y * 64, ks = blockIdx.z;
    const int kbase = ks * (KK / KSPL);

    uint32_t soA[2], soB[4], goA[2], goB[4];
#pragma unroll
    for (int v = 0; v < 2; v++) {
        const int idx = tid + 256 * v, r = idx >> 3, s = idx & 7;
        soA[v] = (uint32_t)(r * (AST * 2) + s * 16);
        goA[v] = (uint32_t)(r * KCAT + s * 8);
    }
#pragma unroll
    for (int v = 0; v < 4; v++) {
        const int idx = tid + 256 * v, r = idx >> 3, s = idx & 7;
        soB[v] = (uint32_t)(ABYT_A + r * (AST * 2) + s * 16);
        goB[v] = (uint32_t)(r * KCAT + s * 8);
    }

    float acc[8][4], run[8][4];
#pragma unroll
    for (int t = 0; t < 8; t++)
#pragma unroll
        for (int r = 0; r < 4; r++) { acc[t][r] = 0.f; run[t][r] = 0.f; }

    for (int g = 0; g < GTR + 2; ++g) {
        if (g < GTR) {
            const int kf = kbase + g / NCH, i0 = (g % NCH) * KC;
            const uint32_t sb = sbase + (g % NST) * STAGE_M;
            const __half* up = g_ucat + (size_t)b0 * KCAT + i0;
            const __half* wp = g_Wr_cat + ((size_t)kf * OLEN + o0) * KCAT + i0;
#pragma unroll
            for (int v = 0; v < 2; v++) cpa16(sb + soA[v], up + goA[v]);
#pragma unroll
            for (int v = 0; v < 4; v++) cpa16(sb + soB[v], wp + goB[v]);
        }
        asm volatile("cp.async.commit_group;" ::: "memory");
        if (g >= 2) {
            const int gm = g - 2;
            asm volatile("cp.async.wait_group 2;" ::: "memory");
            __syncthreads();
            const uint32_t Ab = sbase + (gm % NST) * STAGE_M;
            const uint32_t Bb = Ab + ABYT_A;
#pragma unroll
            for (int kq = 0; kq < 4; kq++) {
                uint32_t a[2][4], b[2][4];
#pragma unroll
                for (int mi = 0; mi < 2; mi++) {
                    const int row = wm * 32 + mi * 16 + (lane & 15);
                    const uint32_t ad = Ab + row * (AST * 2) + kq * 32 + ((lane >> 4) & 1) * 16;
                    ldsm4(ad, a[mi][0], a[mi][1], a[mi][2], a[mi][3]);
                }
#pragma unroll
                for (int np = 0; np < 2; np++) {
                    const int row = wn * 32 + np * 16 + ((lane >> 4) & 1) * 8 + (lane & 7);
                    const uint32_t bd = Bb + row * (AST * 2) + kq * 32 + ((lane >> 3) & 1) * 16;
                    ldsm4(bd, b[np][0], b[np][1], b[np][2], b[np][3]);
                }
#pragma unroll
                for (int mi = 0; mi < 2; mi++)
#pragma unroll
                    for (int ni = 0; ni < 4; ni++)
                        mma16816(acc[mi * 4 + ni], a[mi], &b[ni >> 1][(ni & 1) * 2]);
            }
            if (gm % NCH == NCH - 1) {
                const int k = kbase + gm / NCH;
#pragma unroll
                for (int mi = 0; mi < 2; mi++) {
                    const int r0 = b0 + wm * 32 + mi * 16 + (lane >> 2);
                    const float w0 = __ldg(&member[(size_t)r0 * KK + k]);
                    const float w1 = __ldg(&member[(size_t)(r0 + 8) * KK + k]);
#pragma unroll
                    for (int ni = 0; ni < 4; ni++) {
                        float* A_ = acc[mi * 4 + ni];
                        float* R_ = run[mi * 4 + ni];
                        R_[0] = fmaf(w0, fabsf(A_[0]), R_[0]);
                        R_[1] = fmaf(w0, fabsf(A_[1]), R_[1]);
                        R_[2] = fmaf(w1, fabsf(A_[2]), R_[2]);
                        R_[3] = fmaf(w1, fabsf(A_[3]), R_[3]);
                        A_[0] = A_[1] = A_[2] = A_[3] = 0.f;
                    }
                }
            }
        }
    }

    float* ob = g_xp[ks];
#pragma unroll
    for (int mi = 0; mi < 2; mi++)
#pragma unroll
        for (int ni = 0; ni < 4; ni++) {
            const int row = b0 + wm * 32 + mi * 16 + (lane >> 2);
            const int col = o0 + wn * 32 + ni * 8 + 2 * (lane & 3);
            *(float2*)&ob[(size_t)row * OLEN + col] =
                make_float2(run[mi * 4 + ni][0], run[mi * 4 + ni][1]);
            *(float2*)&ob[(size_t)(row + 8) * OLEN + col] =
                make_float2(run[mi * 4 + ni][2], run[mi * 4 + ni][3]);
        }
}

// ---------------- gathered Wc GEMM (top-2 psi entries) ----------------
__global__ void __launch_bounds__(256, 1)
gather_mma(float* __restrict__ out)
{
    if ((int)blockIdx.y >= g_nseg) return;
    extern __shared__ char dyn[];
    const uint32_t sbase = smem_u32(dyn);
    __shared__ int   rowb[128];
    __shared__ float roww[128];
    const int tid = threadIdx.x, lane = tid & 31, wid = tid >> 5;
    const int wm = wid >> 2, wn = wid & 3;
    const int o0 = blockIdx.x * 128;
    const int4 sgd = g_segs[blockIdx.y];
    const int k = sgd.x, ebase = sgd.y, rows = sgd.z;

    if (tid < 128) {
        if (tid < rows) {
            int2 e = g_eb[(size_t)ebase + tid];
            rowb[tid] = e.x; roww[tid] = __int_as_float(e.y);
        } else { rowb[tid] = 0; roww[tid] = 0.f; }
    }
    __syncthreads();

    float acc[16][4];
#pragma unroll
    for (int t = 0; t < 16; t++)
#pragma unroll
        for (int r = 0; r < 4; r++) acc[t][r] = 0.f;

    for (int g = 0; g < NCH + 2; ++g) {
        __syncthreads();
        if (g < NCH) {
            const int i0 = g * KC;
            const uint32_t sb = sbase + (g % 3) * STAGE_G;
#pragma unroll
            for (int v = 0; v < 4; v++) {
                const int idx = tid + 256 * v, r = idx >> 3, s = idx & 7;
                const uint32_t off = (uint32_t)(r * (AST * 2) + s * 16);
                cpa16(sb + off, g_ucat + (size_t)rowb[r] * KCAT + i0 + s * 8);
                cpa16(sb + ABYT_B + off,
                      g_Wc_cat + ((size_t)k * OLEN + o0 + r) * KCAT + i0 + s * 8);
            }
        }
        asm volatile("cp.async.commit_group;" ::: "memory");
        if (g >= 2) {
            const int gm = g - 2;
            asm volatile("cp.async.wait_group 2;" ::: "memory");
            __syncthreads();
            const uint32_t Ab = sbase + (gm % 3) * STAGE_G;
            const uint32_t Bb = Ab + ABYT_B;
#pragma unroll
            for (int kq = 0; kq < 4; kq++) {
                uint32_t a[4][4], b[2][4];
#pragma unroll
                for (int mi = 0; mi < 4; mi++) {
                    const int row = wm * 64 + mi * 16 + (lane & 15);
                    const uint32_t ad = Ab + row * (AST * 2) + kq * 32 + ((lane >> 4) & 1) * 16;
                    ldsm4(ad, a[mi][0], a[mi][1], a[mi][2], a[mi][3]);
                }
#pragma unroll
                for (int np = 0; np < 2; np++) {
                    const int row = wn * 32 + np * 16 + ((lane >> 4) & 1) * 8 + (lane & 7);
                    const uint32_t bd = Bb + row * (AST * 2) + kq * 32 + ((lane >> 3) & 1) * 16;
                    ldsm4(bd, b[np][0], b[np][1], b[np][2], b[np][3]);
                }
#pragma unroll
                for (int mi = 0; mi < 4; mi++)
#pragma unroll
                    for (int ni = 0; ni < 4; ni++)
                        mma16816(acc[mi * 4 + ni], a[mi], &b[ni >> 1][(ni & 1) * 2]);
            }
        }
    }

#pragma unroll
    for (int mi = 0; mi < 4; mi++) {
        const int lr0 = wm * 64 + mi * 16 + (lane >> 2);
        const int lr1 = lr0 + 8;
        const float w0 = roww[lr0], w1 = roww[lr1];
        const int   bb0 = rowb[lr0], bb1 = rowb[lr1];
#pragma unroll
        for (int ni = 0; ni < 4; ni++) {
            const int col = o0 + wn * 32 + ni * 8 + 2 * (lane & 3);
            float* A_ = acc[mi * 4 + ni];
            if (w0 != 0.f) {
                atomicAdd(&out[(size_t)bb0 * OLEN + col],     w0 * fabsf(A_[0]));
                atomicAdd(&out[(size_t)bb0 * OLEN + col + 1], w0 * fabsf(A_[1]));
            }
            if (w1 != 0.f) {
                atomicAdd(&out[(size_t)bb1 * OLEN + col],     w1 * fabsf(A_[2]));
                atomicAdd(&out[(size_t)bb1 * OLEN + col + 1], w1 * fabsf(A_[3]));
            }
        }
    }
}

// =================================================================
extern "C" void kernel_launch(void* const* d_in, const int* in_sizes, int n_in,
                              void* d_out, int out_size)
{
    const float* z   = (const float*)d_in[0];
    const float* u   = (const float*)d_in[1];
    const float* mem = (const float*)d_in[2];
    const float* mu  = (const float*)d_in[3];
    const float* sig = (const float*)d_in[4];
    const float* Wc  = (const float*)d_in[5];
    const float* Wr  = (const float*)d_in[6];
    float* out = (float*)d_out;

    cudaFuncSetAttribute(main_mma,   cudaFuncAttributeMaxDynamicSharedMemorySize, SMEMM);
    cudaFuncSetAttribute(gather_mma, cudaFuncAttributeMaxDynamicSharedMemorySize, SMEMG);

    conv_all<<<NB_W + NB_U + NB_Z, 256>>>(Wr, u, out);                   // 1
    convw_kernel<<<NB_W, 256>>>(Wc, 0);                                  // 2
    main_mma<<<dim3(OLEN / 128, BATCH / 64, KSPL), 256, SMEMM>>>(mem);   // 3
    d2_kernel<<<dim3(KK, BATCH / 32), 128>>>(z, mu, sig);                // 4 <- ncu
    top2_kernel<<<BATCH * 32 / 256, 256>>>();                            // 5
    seg_kernel<<<1, 32>>>();                                             // 6
    addx_kernel<<<(BATCH * OLEN / 4) / 256, 256>>>(out);                 // 7
    gather_mma<<<dim3(OLEN / 128, MAXSEG), 256, SMEMG>>>(out);           // 8
}